// round 3
// baseline (speedup 1.0000x reference)
#include <cuda_runtime.h>
#include <math.h>

#define EPS 1e-8f

struct V3 { float x, y, z; };
struct Q4 { float x, y, z, w; };

__device__ __forceinline__ V3 v3(float x, float y, float z) { V3 r; r.x=x; r.y=y; r.z=z; return r; }
__device__ __forceinline__ V3 vadd(V3 a, V3 b) { return v3(a.x+b.x, a.y+b.y, a.z+b.z); }
__device__ __forceinline__ V3 vsub(V3 a, V3 b) { return v3(a.x-b.x, a.y-b.y, a.z-b.z); }
__device__ __forceinline__ V3 vscale(V3 a, float s) { return v3(a.x*s, a.y*s, a.z*s); }
__device__ __forceinline__ float vdot(V3 a, V3 b) { return fmaf(a.x,b.x, fmaf(a.y,b.y, a.z*b.z)); }
__device__ __forceinline__ V3 vcross(V3 a, V3 b) {
    return v3(a.y*b.z - a.z*b.y,
              a.z*b.x - a.x*b.z,
              a.x*b.y - a.y*b.x);
}

__device__ __forceinline__ Q4 qconj(Q4 q) { Q4 r; r.x=-q.x; r.y=-q.y; r.z=-q.z; r.w=q.w; return r; }

__device__ __forceinline__ Q4 qmul(Q4 q, Q4 r) {
    Q4 o;
    V3 qv = v3(q.x,q.y,q.z), rv = v3(r.x,r.y,r.z);
    V3 c = vcross(qv, rv);
    o.x = q.w*r.x + r.w*q.x + c.x;
    o.y = q.w*r.y + r.w*q.y + c.y;
    o.z = q.w*r.z + r.w*q.z + c.z;
    o.w = q.w*r.w - vdot(qv, rv);
    return o;
}

__device__ __forceinline__ V3 qrot(Q4 q, V3 v) {
    V3 qv = v3(q.x,q.y,q.z);
    V3 t = vscale(vcross(qv, v), 2.0f);
    return vadd(vadd(v, vscale(t, q.w)), vcross(qv, t));
}

__device__ __forceinline__ V3 so3_log(Q4 q) {
    V3 v = v3(q.x,q.y,q.z);
    float n2 = vdot(v, v);
    float n = sqrtf(n2);
    float theta = 2.0f * atan2f(n, q.w);
    float k;
    if (n > EPS) {
        k = theta / n;
    } else {
        float wd = (fabsf(q.w) > EPS) ? q.w : 1.0f;
        k = 2.0f / wd;
    }
    return vscale(v, k);
}

__device__ __forceinline__ void se3_log(V3 t, Q4 q, V3* tau, V3* phi_out) {
    V3 phi = so3_log(q);
    float theta2 = vdot(phi, phi);
    float theta = sqrtf(theta2);
    float coef;
    if (theta < 1e-4f) {
        coef = 1.0f / 12.0f;
    } else {
        float s, c;
        sincosf(theta, &s, &c);
        coef = 1.0f / theta2 - (1.0f + c) / (2.0f * theta * s);
    }
    V3 pxt = vcross(phi, t);
    *tau = vadd(vsub(t, vscale(pxt, 0.5f)), vscale(vcross(phi, pxt), coef));
    *phi_out = phi;
}

// Shared buffer layout (per warp): 96 rows x 9 floats.
//   rows  0..31 : n1 node rows (7 floats used)
//   rows 32..63 : n2 node rows
//   rows 64..95 : pose rows
// Stride 9 is coprime with 32 -> conflict-free per-lane row reads.
#define ROWS_PER_WARP 96
#define ROW_STRIDE 9
#define WARPS_PER_BLOCK 8

__global__ __launch_bounds__(256)
void fused_kernel(const int*   __restrict__ edges,
                  const float* __restrict__ nodes,
                  const float* __restrict__ vels,
                  const float* __restrict__ poses,
                  const float* __restrict__ imu_drots,
                  const float* __restrict__ imu_dtrans,
                  const float* __restrict__ imu_dvels,
                  const float* __restrict__ dts,
                  float* __restrict__ out_pg,
                  float* __restrict__ out_adjvel,
                  float* __restrict__ out_imurot,
                  float* __restrict__ out_transvel,
                  int E, int M, int edgeBlocks)
{
    __shared__ float buf[WARPS_PER_BLOCK][ROWS_PER_WARP * ROW_STRIDE];
    __shared__ int   sidx[WARPS_PER_BLOCK][64];

    if ((int)blockIdx.x < edgeBlocks) {
        int wib  = threadIdx.x >> 5;
        int lane = threadIdx.x & 31;
        float* wbuf = buf[wib];
        int*   widx = sidx[wib];

        long long warp_global = (long long)blockIdx.x * WARPS_PER_BLOCK + wib;
        int e_base = (int)(warp_global * 32);
        if (e_base >= E) return;
        int nvalid = min(32, E - e_base);
        bool valid = lane < nvalid;
        int e = e_base + lane;

        // 1) coalesced index load (int2/lane), stash in smem
        int2 idp = valid ? *reinterpret_cast<const int2*>(edges + 2 * (size_t)e)
                         : make_int2(0, 0);
        widx[lane]      = idp.x;
        widx[32 + lane] = idp.y;
        __syncwarp();

        // 2) cooperative node gather: 64 rows x 7 floats = 448 loads
        //    consecutive lanes hit consecutive addresses within a row
        #pragma unroll
        for (int k = 0; k < 14; k++) {
            int f = lane + k * 32;          // 0..447
            int row = f / 7;
            int col = f - row * 7;
            int ni = widx[row];
            wbuf[row * ROW_STRIDE + col] = __ldg(nodes + (size_t)ni * 7 + col);
        }

        // 3) coalesced pose stage: 32 rows x 7 floats = 224 loads
        const float* pbase = poses + (size_t)e_base * 7;
        int plim = nvalid * 7;
        #pragma unroll
        for (int k = 0; k < 7; k++) {
            int f = lane + k * 32;          // 0..223
            if (f < plim) {
                int row = f / 7;
                int col = f - row * 7;
                wbuf[(64 + row) * ROW_STRIDE + col] = pbase[f];
            }
        }
        __syncwarp();

        // 4) per-lane compute from smem (conflict-free)
        if (valid) {
            const float* r1 = wbuf + lane * ROW_STRIDE;
            const float* r2 = wbuf + (32 + lane) * ROW_STRIDE;
            const float* rp = wbuf + (64 + lane) * ROW_STRIDE;

            V3 t1 = v3(r1[0], r1[1], r1[2]);
            Q4 q1; q1.x=r1[3]; q1.y=r1[4]; q1.z=r1[5]; q1.w=r1[6];
            V3 t2 = v3(r2[0], r2[1], r2[2]);
            Q4 q2; q2.x=r2[3]; q2.y=r2[4]; q2.z=r2[5]; q2.w=r2[6];
            V3 tp = v3(rp[0], rp[1], rp[2]);
            Q4 qp; qp.x=rp[3]; qp.y=rp[4]; qp.z=rp[5]; qp.w=rp[6];

            Q4 qi1 = qconj(q1);
            V3 ti1 = vscale(qrot(qi1, t1), -1.0f);
            Q4 qa  = qmul(qi1, q2);
            V3 ta  = vadd(ti1, qrot(qi1, t2));

            Q4 qip = qconj(qp);
            V3 tip = vscale(qrot(qip, tp), -1.0f);
            Q4 qe  = qmul(qip, qa);
            V3 te  = vadd(tip, qrot(qip, ta));

            V3 tau, phi;
            se3_log(te, qe, &tau, &phi);

            // 5) stage result in own row (only this lane touches row `lane`)
            float* ro = wbuf + lane * ROW_STRIDE;
            ro[0] = tau.x; ro[1] = tau.y; ro[2] = tau.z;
            ro[3] = phi.x; ro[4] = phi.y; ro[5] = phi.z;
        }
        __syncwarp();

        // 6) coalesced output store: 32 rows x 6 floats = 192 stores
        float* obase = out_pg + (size_t)e_base * 6;
        int olim = nvalid * 6;
        #pragma unroll
        for (int k = 0; k < 6; k++) {
            int f = lane + k * 32;          // 0..191
            if (f < olim) {
                int row = f / 6;
                int col = f - row * 6;
                obase[f] = wbuf[row * ROW_STRIDE + col];
            }
        }
    } else {
        // ---- node path ----
        int i = (blockIdx.x - edgeBlocks) * blockDim.x + threadIdx.x;
        if (i >= M) return;

        const float* n0 = nodes + (size_t)i * 7;
        float a0=n0[0], a1=n0[1], a2=n0[2], a3=n0[3], a4=n0[4], a5=n0[5], a6=n0[6];
        float b0=n0[7], b1=n0[8], b2=n0[9], b3=n0[10], b4=n0[11], b5=n0[12], b6=n0[13];

        float v0x=vels[3*i+0], v0y=vels[3*i+1], v0z=vels[3*i+2];
        float v1x=vels[3*i+3], v1y=vels[3*i+4], v1z=vels[3*i+5];

        float4 drq = *reinterpret_cast<const float4*>(imu_drots + 4 * (size_t)i);
        float dvx=imu_dvels[3*i+0], dvy=imu_dvels[3*i+1], dvz=imu_dvels[3*i+2];
        float dtx=imu_dtrans[3*i+0], dty=imu_dtrans[3*i+1], dtz=imu_dtrans[3*i+2];
        float dt = dts[i];

        V3 t0 = v3(a0,a1,a2), t1 = v3(b0,b1,b2);
        Q4 q0; q0.x=a3; q0.y=a4; q0.z=a5; q0.w=a6;
        Q4 q1; q1.x=b3; q1.y=b4; q1.z=b5; q1.w=b6;

        out_adjvel[3*i+0] = 0.1f * (dvx - (v1x - v0x));
        out_adjvel[3*i+1] = 0.1f * (dvy - (v1y - v0y));
        out_adjvel[3*i+2] = 0.1f * (dvz - (v1z - v0z));

        Q4 dr; dr.x=drq.x; dr.y=drq.y; dr.z=drq.z; dr.w=drq.w;
        Q4 qre = qmul(qconj(dr), qmul(qconj(q0), q1));
        V3 rot = so3_log(qre);
        out_imurot[3*i+0] = rot.x;
        out_imurot[3*i+1] = rot.y;
        out_imurot[3*i+2] = rot.z;

        out_transvel[3*i+0] = 0.1f * (t1.x - t0.x - fmaf(v0x, dt, dtx));
        out_transvel[3*i+1] = 0.1f * (t1.y - t0.y - fmaf(v0y, dt, dty));
        out_transvel[3*i+2] = 0.1f * (t1.z - t0.z - fmaf(v0z, dt, dtz));
    }
}

extern "C" void kernel_launch(void* const* d_in, const int* in_sizes, int n_in,
                              void* d_out, int out_size) {
    const int*   edges      = (const int*)  d_in[0];
    const float* nodes      = (const float*)d_in[1];
    const float* vels       = (const float*)d_in[2];
    const float* poses      = (const float*)d_in[3];
    const float* imu_drots  = (const float*)d_in[4];
    const float* imu_dtrans = (const float*)d_in[5];
    const float* imu_dvels  = (const float*)d_in[6];
    const float* dts        = (const float*)d_in[7];

    int E = in_sizes[0] / 2;
    int N = in_sizes[1] / 7;
    int M = N - 1;

    float* out = (float*)d_out;
    float* out_pg       = out;
    float* out_adjvel   = out + (size_t)6 * E;
    float* out_imurot   = out_adjvel + (size_t)3 * M;
    float* out_transvel = out_imurot + (size_t)3 * M;

    const int TPB = 256;
    int nEdgeWarps = (E + 31) / 32;
    int edgeBlocks = (nEdgeWarps + WARPS_PER_BLOCK - 1) / WARPS_PER_BLOCK;
    int nodeBlocks = (M + TPB - 1) / TPB;

    fused_kernel<<<edgeBlocks + nodeBlocks, TPB>>>(
        edges, nodes, vels, poses, imu_drots, imu_dtrans, imu_dvels, dts,
        out_pg, out_adjvel, out_imurot, out_transvel,
        E, M, edgeBlocks);
}

// round 4
// speedup vs baseline: 1.1804x; 1.1804x over previous
#include <cuda_runtime.h>
#include <math.h>

#define EPS 1e-8f

struct V3 { float x, y, z; };
struct Q4 { float x, y, z, w; };

__device__ __forceinline__ V3 v3(float x, float y, float z) { V3 r; r.x=x; r.y=y; r.z=z; return r; }
__device__ __forceinline__ V3 vadd(V3 a, V3 b) { return v3(a.x+b.x, a.y+b.y, a.z+b.z); }
__device__ __forceinline__ V3 vsub(V3 a, V3 b) { return v3(a.x-b.x, a.y-b.y, a.z-b.z); }
__device__ __forceinline__ V3 vscale(V3 a, float s) { return v3(a.x*s, a.y*s, a.z*s); }
__device__ __forceinline__ float vdot(V3 a, V3 b) { return fmaf(a.x,b.x, fmaf(a.y,b.y, a.z*b.z)); }
__device__ __forceinline__ V3 vcross(V3 a, V3 b) {
    return v3(a.y*b.z - a.z*b.y,
              a.z*b.x - a.x*b.z,
              a.x*b.y - a.y*b.x);
}

__device__ __forceinline__ Q4 qconj(Q4 q) { Q4 r; r.x=-q.x; r.y=-q.y; r.z=-q.z; r.w=q.w; return r; }

__device__ __forceinline__ Q4 qmul(Q4 q, Q4 r) {
    Q4 o;
    V3 qv = v3(q.x,q.y,q.z), rv = v3(r.x,r.y,r.z);
    V3 c = vcross(qv, rv);
    o.x = q.w*r.x + r.w*q.x + c.x;
    o.y = q.w*r.y + r.w*q.y + c.y;
    o.z = q.w*r.z + r.w*q.z + c.z;
    o.w = q.w*r.w - vdot(qv, rv);
    return o;
}

__device__ __forceinline__ V3 qrot(Q4 q, V3 v) {
    V3 qv = v3(q.x,q.y,q.z);
    V3 t = vscale(vcross(qv, v), 2.0f);
    return vadd(vadd(v, vscale(t, q.w)), vcross(qv, t));
}

__device__ __forceinline__ V3 so3_log(Q4 q) {
    V3 v = v3(q.x,q.y,q.z);
    float n2 = vdot(v, v);
    float n = sqrtf(n2);
    float theta = 2.0f * atan2f(n, q.w);
    float k;
    if (n > EPS) {
        k = theta / n;
    } else {
        float wd = (fabsf(q.w) > EPS) ? q.w : 1.0f;
        k = 2.0f / wd;
    }
    return vscale(v, k);
}

__device__ __forceinline__ void se3_log(V3 t, Q4 q, V3* tau, V3* phi_out) {
    V3 phi = so3_log(q);
    float theta2 = vdot(phi, phi);
    float theta = sqrtf(theta2);
    float coef;
    if (theta < 1e-4f) {
        coef = 1.0f / 12.0f;
    } else {
        float s, c;
        sincosf(theta, &s, &c);
        coef = 1.0f / theta2 - (1.0f + c) / (2.0f * theta * s);
    }
    V3 pxt = vcross(phi, t);
    *tau = vadd(vsub(t, vscale(pxt, 0.5f)), vscale(vcross(phi, pxt), coef));
    *phi_out = phi;
}

// --- Vectorized 7-float row fetch: 3 aligned float4 loads (third predicated) ---
struct Row12 { float4 r0, r1, r2; int off; };

__device__ __forceinline__ Row12 fetch_row_vec(const float4* __restrict__ p4, size_t row_idx) {
    Row12 r;
    size_t base = row_idx * 7;
    size_t a = base >> 2;
    r.off = (int)(base & 3);
    r.r0 = __ldg(p4 + a);
    r.r1 = __ldg(p4 + a + 1);
    r.r2 = (r.off >= 2) ? __ldg(p4 + a + 2) : r.r1;   // predicated; only used when off>=2
    return r;
}

// Branchless extraction of 7 floats starting at offset `off` in {r0,r1,r2}
__device__ __forceinline__ void extract7(const Row12& rr, V3* t, Q4* q) {
    float s0=rr.r0.x, s1=rr.r0.y, s2=rr.r0.z, s3=rr.r0.w;
    float s4=rr.r1.x, s5=rr.r1.y, s6=rr.r1.z, s7=rr.r1.w;
    float s8=rr.r2.x, s9=rr.r2.y;
    bool o2 = (rr.off & 2) != 0;
    bool o1 = (rr.off & 1) != 0;
    // level 1: shift by 2 if o2
    float u0 = o2 ? s2 : s0;
    float u1 = o2 ? s3 : s1;
    float u2 = o2 ? s4 : s2;
    float u3 = o2 ? s5 : s3;
    float u4 = o2 ? s6 : s4;
    float u5 = o2 ? s7 : s5;
    float u6 = o2 ? s8 : s6;
    float u7 = o2 ? s9 : s7;
    // level 2: shift by 1 if o1
    float v0 = o1 ? u1 : u0;
    float v1 = o1 ? u2 : u1;
    float v2 = o1 ? u3 : u2;
    float v3f = o1 ? u4 : u3;
    float v4 = o1 ? u5 : u4;
    float v5 = o1 ? u6 : u5;
    float v6 = o1 ? u7 : u6;
    t->x = v0; t->y = v1; t->z = v2;
    q->x = v3f; q->y = v4; q->z = v5; q->w = v6;
}

// Scalar fallback (used when 7N % 4 != 0, to avoid OOB on the tail row)
__device__ __forceinline__ void fetch_row_scalar(const float* __restrict__ p, size_t row_idx,
                                                 V3* t, Q4* q) {
    const float* r = p + row_idx * 7;
    t->x = __ldg(r+0); t->y = __ldg(r+1); t->z = __ldg(r+2);
    q->x = __ldg(r+3); q->y = __ldg(r+4); q->z = __ldg(r+5); q->w = __ldg(r+6);
}

template<bool VEC>
__global__ __launch_bounds__(256)
void fused_kernel(const int*   __restrict__ edges,
                  const float* __restrict__ nodes,
                  const float* __restrict__ vels,
                  const float* __restrict__ poses,
                  const float* __restrict__ imu_drots,
                  const float* __restrict__ imu_dtrans,
                  const float* __restrict__ imu_dvels,
                  const float* __restrict__ dts,
                  float* __restrict__ out_pg,
                  float* __restrict__ out_adjvel,
                  float* __restrict__ out_imurot,
                  float* __restrict__ out_transvel,
                  int E, int M, int edgeBlocks)
{
    if ((int)blockIdx.x < edgeBlocks) {
        int e = blockIdx.x * blockDim.x + threadIdx.x;
        if (e >= E) return;

        int2 id = __ldg(reinterpret_cast<const int2*>(edges) + e);

        V3 t1, t2, tp;
        Q4 q1, q2, qp;

        if (VEC) {
            const float4* n4 = reinterpret_cast<const float4*>(nodes);
            const float4* p4 = reinterpret_cast<const float4*>(poses);
            // issue all loads first for MLP
            Row12 ra = fetch_row_vec(n4, (size_t)id.x);
            Row12 rb = fetch_row_vec(n4, (size_t)id.y);
            Row12 rp = fetch_row_vec(p4, (size_t)e);
            extract7(ra, &t1, &q1);
            extract7(rb, &t2, &q2);
            extract7(rp, &tp, &qp);
        } else {
            fetch_row_scalar(nodes, (size_t)id.x, &t1, &q1);
            fetch_row_scalar(nodes, (size_t)id.y, &t2, &q2);
            fetch_row_scalar(poses, (size_t)e,    &tp, &qp);
        }

        Q4 qi1 = qconj(q1);
        V3 ti1 = vscale(qrot(qi1, t1), -1.0f);
        Q4 qa  = qmul(qi1, q2);
        V3 ta  = vadd(ti1, qrot(qi1, t2));

        Q4 qip = qconj(qp);
        V3 tip = vscale(qrot(qip, tp), -1.0f);
        Q4 qe  = qmul(qip, qa);
        V3 te  = vadd(tip, qrot(qip, ta));

        V3 tau, phi;
        se3_log(te, qe, &tau, &phi);

        float* o = out_pg + (size_t)e * 6;
        o[0] = tau.x; o[1] = tau.y; o[2] = tau.z;
        o[3] = phi.x; o[4] = phi.y; o[5] = phi.z;
    } else {
        // ---- node path ----
        int i = (blockIdx.x - edgeBlocks) * blockDim.x + threadIdx.x;
        if (i >= M) return;

        const float* n0 = nodes + (size_t)i * 7;
        float a0=n0[0], a1=n0[1], a2=n0[2], a3=n0[3], a4=n0[4], a5=n0[5], a6=n0[6];
        float b0=n0[7], b1=n0[8], b2=n0[9], b3=n0[10], b4=n0[11], b5=n0[12], b6=n0[13];

        float v0x=vels[3*i+0], v0y=vels[3*i+1], v0z=vels[3*i+2];
        float v1x=vels[3*i+3], v1y=vels[3*i+4], v1z=vels[3*i+5];

        float4 drq = *reinterpret_cast<const float4*>(imu_drots + 4 * (size_t)i);
        float dvx=imu_dvels[3*i+0], dvy=imu_dvels[3*i+1], dvz=imu_dvels[3*i+2];
        float dtx=imu_dtrans[3*i+0], dty=imu_dtrans[3*i+1], dtz=imu_dtrans[3*i+2];
        float dt = dts[i];

        V3 t0 = v3(a0,a1,a2), t1 = v3(b0,b1,b2);
        Q4 q0; q0.x=a3; q0.y=a4; q0.z=a5; q0.w=a6;
        Q4 q1; q1.x=b3; q1.y=b4; q1.z=b5; q1.w=b6;

        out_adjvel[3*i+0] = 0.1f * (dvx - (v1x - v0x));
        out_adjvel[3*i+1] = 0.1f * (dvy - (v1y - v0y));
        out_adjvel[3*i+2] = 0.1f * (dvz - (v1z - v0z));

        Q4 dr; dr.x=drq.x; dr.y=drq.y; dr.z=drq.z; dr.w=drq.w;
        Q4 qre = qmul(qconj(dr), qmul(qconj(q0), q1));
        V3 rot = so3_log(qre);
        out_imurot[3*i+0] = rot.x;
        out_imurot[3*i+1] = rot.y;
        out_imurot[3*i+2] = rot.z;

        out_transvel[3*i+0] = 0.1f * (t1.x - t0.x - fmaf(v0x, dt, dtx));
        out_transvel[3*i+1] = 0.1f * (t1.y - t0.y - fmaf(v0y, dt, dty));
        out_transvel[3*i+2] = 0.1f * (t1.z - t0.z - fmaf(v0z, dt, dtz));
    }
}

extern "C" void kernel_launch(void* const* d_in, const int* in_sizes, int n_in,
                              void* d_out, int out_size) {
    const int*   edges      = (const int*)  d_in[0];
    const float* nodes      = (const float*)d_in[1];
    const float* vels       = (const float*)d_in[2];
    const float* poses      = (const float*)d_in[3];
    const float* imu_drots  = (const float*)d_in[4];
    const float* imu_dtrans = (const float*)d_in[5];
    const float* imu_dvels  = (const float*)d_in[6];
    const float* dts        = (const float*)d_in[7];

    int E = in_sizes[0] / 2;
    int N = in_sizes[1] / 7;
    int M = N - 1;

    float* out = (float*)d_out;
    float* out_pg       = out;
    float* out_adjvel   = out + (size_t)6 * E;
    float* out_imurot   = out_adjvel + (size_t)3 * M;
    float* out_transvel = out_imurot + (size_t)3 * M;

    const int TPB = 256;
    int edgeBlocks = (E + TPB - 1) / TPB;
    int nodeBlocks = (M + TPB - 1) / TPB;

    // Vector path needs the float-counts of nodes and poses to be 4-divisible
    // so the covering float4 loads never go out of bounds.
    bool vec_ok = ((in_sizes[1] & 3) == 0) && ((in_sizes[3] & 3) == 0);

    if (vec_ok) {
        fused_kernel<true><<<edgeBlocks + nodeBlocks, TPB>>>(
            edges, nodes, vels, poses, imu_drots, imu_dtrans, imu_dvels, dts,
            out_pg, out_adjvel, out_imurot, out_transvel,
            E, M, edgeBlocks);
    } else {
        fused_kernel<false><<<edgeBlocks + nodeBlocks, TPB>>>(
            edges, nodes, vels, poses, imu_drots, imu_dtrans, imu_dvels, dts,
            out_pg, out_adjvel, out_imurot, out_transvel,
            E, M, edgeBlocks);
    }
}

// round 5
// speedup vs baseline: 1.2920x; 1.0945x over previous
#include <cuda_runtime.h>
#include <math.h>

#define EPS 1e-8f
#define MAX_NODES 1048576

// 32MB padded node scratch: row i -> g_nodes8[2i] = {t.x,t.y,t.z,q.x}, g_nodes8[2i+1] = {q.y,q.z,q.w,pad}
__device__ float4 g_nodes8[(size_t)MAX_NODES * 2];

struct V3 { float x, y, z; };
struct Q4 { float x, y, z, w; };

__device__ __forceinline__ V3 v3(float x, float y, float z) { V3 r; r.x=x; r.y=y; r.z=z; return r; }
__device__ __forceinline__ V3 vadd(V3 a, V3 b) { return v3(a.x+b.x, a.y+b.y, a.z+b.z); }
__device__ __forceinline__ V3 vsub(V3 a, V3 b) { return v3(a.x-b.x, a.y-b.y, a.z-b.z); }
__device__ __forceinline__ V3 vscale(V3 a, float s) { return v3(a.x*s, a.y*s, a.z*s); }
__device__ __forceinline__ float vdot(V3 a, V3 b) { return fmaf(a.x,b.x, fmaf(a.y,b.y, a.z*b.z)); }
__device__ __forceinline__ V3 vcross(V3 a, V3 b) {
    return v3(a.y*b.z - a.z*b.y,
              a.z*b.x - a.x*b.z,
              a.x*b.y - a.y*b.x);
}

__device__ __forceinline__ Q4 qconj(Q4 q) { Q4 r; r.x=-q.x; r.y=-q.y; r.z=-q.z; r.w=q.w; return r; }

__device__ __forceinline__ Q4 qmul(Q4 q, Q4 r) {
    Q4 o;
    V3 qv = v3(q.x,q.y,q.z), rv = v3(r.x,r.y,r.z);
    V3 c = vcross(qv, rv);
    o.x = q.w*r.x + r.w*q.x + c.x;
    o.y = q.w*r.y + r.w*q.y + c.y;
    o.z = q.w*r.z + r.w*q.z + c.z;
    o.w = q.w*r.w - vdot(qv, rv);
    return o;
}

__device__ __forceinline__ V3 qrot(Q4 q, V3 v) {
    V3 qv = v3(q.x,q.y,q.z);
    V3 t = vscale(vcross(qv, v), 2.0f);
    return vadd(vadd(v, vscale(t, q.w)), vcross(qv, t));
}

__device__ __forceinline__ V3 so3_log(Q4 q) {
    V3 v = v3(q.x,q.y,q.z);
    float n2 = vdot(v, v);
    float n = sqrtf(n2);
    float theta = 2.0f * atan2f(n, q.w);
    float k;
    if (n > EPS) {
        k = theta / n;
    } else {
        float wd = (fabsf(q.w) > EPS) ? q.w : 1.0f;
        k = 2.0f / wd;
    }
    return vscale(v, k);
}

__device__ __forceinline__ void se3_log(V3 t, Q4 q, V3* tau, V3* phi_out) {
    V3 phi = so3_log(q);
    float theta2 = vdot(phi, phi);
    float theta = sqrtf(theta2);
    float coef;
    if (theta < 1e-4f) {
        coef = 1.0f / 12.0f;
    } else {
        float s, c;
        sincosf(theta, &s, &c);
        coef = 1.0f / theta2 - (1.0f + c) / (2.0f * theta * s);
    }
    V3 pxt = vcross(phi, t);
    *tau = vadd(vsub(t, vscale(pxt, 0.5f)), vscale(vcross(phi, pxt), coef));
    *phi_out = phi;
}

// --- Vectorized 7-float row fetch for CONTIGUOUS streams: 3 aligned float4 (3rd predicated) ---
struct Row12 { float4 r0, r1, r2; int off; };

__device__ __forceinline__ Row12 fetch_row_vec(const float4* __restrict__ p4, size_t row_idx) {
    Row12 r;
    size_t base = row_idx * 7;
    size_t a = base >> 2;
    r.off = (int)(base & 3);
    r.r0 = __ldg(p4 + a);
    r.r1 = __ldg(p4 + a + 1);
    r.r2 = (r.off >= 2) ? __ldg(p4 + a + 2) : r.r1;
    return r;
}

__device__ __forceinline__ void extract7(const Row12& rr, V3* t, Q4* q) {
    float s0=rr.r0.x, s1=rr.r0.y, s2=rr.r0.z, s3=rr.r0.w;
    float s4=rr.r1.x, s5=rr.r1.y, s6=rr.r1.z, s7=rr.r1.w;
    float s8=rr.r2.x, s9=rr.r2.y;
    bool o2 = (rr.off & 2) != 0;
    bool o1 = (rr.off & 1) != 0;
    float u0 = o2 ? s2 : s0;
    float u1 = o2 ? s3 : s1;
    float u2 = o2 ? s4 : s2;
    float u3 = o2 ? s5 : s3;
    float u4 = o2 ? s6 : s4;
    float u5 = o2 ? s7 : s5;
    float u6 = o2 ? s8 : s6;
    float u7 = o2 ? s9 : s7;
    float v0 = o1 ? u1 : u0;
    float v1 = o1 ? u2 : u1;
    float v2 = o1 ? u3 : u2;
    float v3f = o1 ? u4 : u3;
    float v4 = o1 ? u5 : u4;
    float v5 = o1 ? u6 : u5;
    float v6 = o1 ? u7 : u6;
    t->x = v0; t->y = v1; t->z = v2;
    q->x = v3f; q->y = v4; q->z = v5; q->w = v6;
}

__device__ __forceinline__ void fetch_row_scalar(const float* __restrict__ p, size_t row_idx,
                                                 V3* t, Q4* q) {
    const float* r = p + row_idx * 7;
    t->x = __ldg(r+0); t->y = __ldg(r+1); t->z = __ldg(r+2);
    q->x = __ldg(r+3); q->y = __ldg(r+4); q->z = __ldg(r+5); q->w = __ldg(r+6);
}

// --- Repack kernel: nodes (7 floats/row) -> g_nodes8 (8 floats/row, 16B aligned) ---
__global__ __launch_bounds__(256)
void repack_kernel(const float* __restrict__ nodes, int N, int vec_ok)
{
    int i = blockIdx.x * blockDim.x + threadIdx.x;
    if (i >= N) return;
    V3 t; Q4 q;
    if (vec_ok) {
        Row12 r = fetch_row_vec(reinterpret_cast<const float4*>(nodes), (size_t)i);
        extract7(r, &t, &q);
    } else {
        fetch_row_scalar(nodes, (size_t)i, &t, &q);
    }
    g_nodes8[2*(size_t)i]     = make_float4(t.x, t.y, t.z, q.x);
    g_nodes8[2*(size_t)i + 1] = make_float4(q.y, q.z, q.w, 0.0f);
}

__device__ __forceinline__ void load_row8(size_t i, V3* t, Q4* q) {
    float4 a = __ldg(&g_nodes8[2*i]);
    float4 b = __ldg(&g_nodes8[2*i + 1]);
    t->x = a.x; t->y = a.y; t->z = a.z;
    q->x = a.w; q->y = b.x; q->z = b.y; q->w = b.z;
}

#define WARPS_PER_BLOCK 8

template<bool SCR, bool VEC>
__global__ __launch_bounds__(256)
void fused_kernel(const int*   __restrict__ edges,
                  const float* __restrict__ nodes,
                  const float* __restrict__ vels,
                  const float* __restrict__ poses,
                  const float* __restrict__ imu_drots,
                  const float* __restrict__ imu_dtrans,
                  const float* __restrict__ imu_dvels,
                  const float* __restrict__ dts,
                  float* __restrict__ out_pg,
                  float* __restrict__ out_adjvel,
                  float* __restrict__ out_imurot,
                  float* __restrict__ out_transvel,
                  int E, int M, int edgeBlocks)
{
    __shared__ float sbuf[WARPS_PER_BLOCK][192];

    if ((int)blockIdx.x < edgeBlocks) {
        int e = blockIdx.x * blockDim.x + threadIdx.x;
        int lane = threadIdx.x & 31;
        int wib  = threadIdx.x >> 5;
        int e_base = e - lane;
        if (e_base >= E) return;
        bool valid = e < E;
        bool full_warp = (e_base + 32) <= E;

        V3 tau, phi;
        if (valid) {
            int2 id = __ldg(reinterpret_cast<const int2*>(edges) + e);

            V3 t1, t2, tp;
            Q4 q1, q2, qp;

            if (SCR) {
                load_row8((size_t)id.x, &t1, &q1);
                load_row8((size_t)id.y, &t2, &q2);
            } else if (VEC) {
                const float4* n4 = reinterpret_cast<const float4*>(nodes);
                Row12 ra = fetch_row_vec(n4, (size_t)id.x);
                Row12 rb = fetch_row_vec(n4, (size_t)id.y);
                extract7(ra, &t1, &q1);
                extract7(rb, &t2, &q2);
            } else {
                fetch_row_scalar(nodes, (size_t)id.x, &t1, &q1);
                fetch_row_scalar(nodes, (size_t)id.y, &t2, &q2);
            }

            if (VEC) {
                Row12 rp = fetch_row_vec(reinterpret_cast<const float4*>(poses), (size_t)e);
                extract7(rp, &tp, &qp);
            } else {
                fetch_row_scalar(poses, (size_t)e, &tp, &qp);
            }

            Q4 qi1 = qconj(q1);
            V3 ti1 = vscale(qrot(qi1, t1), -1.0f);
            Q4 qa  = qmul(qi1, q2);
            V3 ta  = vadd(ti1, qrot(qi1, t2));

            Q4 qip = qconj(qp);
            V3 tip = vscale(qrot(qip, tp), -1.0f);
            Q4 qe  = qmul(qip, qa);
            V3 te  = vadd(tip, qrot(qip, ta));

            se3_log(te, qe, &tau, &phi);
        }

        if (full_warp) {
            // stage in smem, then coalesced float4 stores
            float* wb = sbuf[wib];
            wb[lane*6+0] = tau.x; wb[lane*6+1] = tau.y; wb[lane*6+2] = tau.z;
            wb[lane*6+3] = phi.x; wb[lane*6+4] = phi.y; wb[lane*6+5] = phi.z;
            __syncwarp();
            const float4* wb4 = reinterpret_cast<const float4*>(wb);
            float4* ob4 = reinterpret_cast<float4*>(out_pg + (size_t)e_base * 6);
            ob4[lane] = wb4[lane];
            if (lane < 16) ob4[32 + lane] = wb4[32 + lane];
        } else if (valid) {
            float* o = out_pg + (size_t)e * 6;
            o[0] = tau.x; o[1] = tau.y; o[2] = tau.z;
            o[3] = phi.x; o[4] = phi.y; o[5] = phi.z;
        }
    } else {
        // ---- node path ----
        int i = (blockIdx.x - edgeBlocks) * blockDim.x + threadIdx.x;
        if (i >= M) return;

        V3 t0, t1;
        Q4 q0, q1;
        if (SCR) {
            load_row8((size_t)i, &t0, &q0);
            load_row8((size_t)i + 1, &t1, &q1);
        } else {
            const float* n0 = nodes + (size_t)i * 7;
            t0 = v3(n0[0], n0[1], n0[2]);
            q0.x=n0[3]; q0.y=n0[4]; q0.z=n0[5]; q0.w=n0[6];
            t1 = v3(n0[7], n0[8], n0[9]);
            q1.x=n0[10]; q1.y=n0[11]; q1.z=n0[12]; q1.w=n0[13];
        }

        float v0x=vels[3*i+0], v0y=vels[3*i+1], v0z=vels[3*i+2];
        float v1x=vels[3*i+3], v1y=vels[3*i+4], v1z=vels[3*i+5];

        float4 drq = *reinterpret_cast<const float4*>(imu_drots + 4 * (size_t)i);
        float dvx=imu_dvels[3*i+0], dvy=imu_dvels[3*i+1], dvz=imu_dvels[3*i+2];
        float dtx=imu_dtrans[3*i+0], dty=imu_dtrans[3*i+1], dtz=imu_dtrans[3*i+2];
        float dt = dts[i];

        out_adjvel[3*i+0] = 0.1f * (dvx - (v1x - v0x));
        out_adjvel[3*i+1] = 0.1f * (dvy - (v1y - v0y));
        out_adjvel[3*i+2] = 0.1f * (dvz - (v1z - v0z));

        Q4 dr; dr.x=drq.x; dr.y=drq.y; dr.z=drq.z; dr.w=drq.w;
        Q4 qre = qmul(qconj(dr), qmul(qconj(q0), q1));
        V3 rot = so3_log(qre);
        out_imurot[3*i+0] = rot.x;
        out_imurot[3*i+1] = rot.y;
        out_imurot[3*i+2] = rot.z;

        out_transvel[3*i+0] = 0.1f * (t1.x - t0.x - fmaf(v0x, dt, dtx));
        out_transvel[3*i+1] = 0.1f * (t1.y - t0.y - fmaf(v0y, dt, dty));
        out_transvel[3*i+2] = 0.1f * (t1.z - t0.z - fmaf(v0z, dt, dtz));
    }
}

extern "C" void kernel_launch(void* const* d_in, const int* in_sizes, int n_in,
                              void* d_out, int out_size) {
    const int*   edges      = (const int*)  d_in[0];
    const float* nodes      = (const float*)d_in[1];
    const float* vels       = (const float*)d_in[2];
    const float* poses      = (const float*)d_in[3];
    const float* imu_drots  = (const float*)d_in[4];
    const float* imu_dtrans = (const float*)d_in[5];
    const float* imu_dvels  = (const float*)d_in[6];
    const float* dts        = (const float*)d_in[7];

    int E = in_sizes[0] / 2;
    int N = in_sizes[1] / 7;
    int M = N - 1;

    float* out = (float*)d_out;
    float* out_pg       = out;
    float* out_adjvel   = out + (size_t)6 * E;
    float* out_imurot   = out_adjvel + (size_t)3 * M;
    float* out_transvel = out_imurot + (size_t)3 * M;

    const int TPB = 256;
    int edgeBlocks = (E + TPB - 1) / TPB;
    int nodeBlocks = (M + TPB - 1) / TPB;

    bool nodes_vec_ok = ((in_sizes[1] & 3) == 0);
    bool poses_vec_ok = ((in_sizes[3] & 3) == 0);
    bool scr_ok = (N <= MAX_NODES);

    if (scr_ok) {
        repack_kernel<<<(N + TPB - 1) / TPB, TPB>>>(nodes, N, nodes_vec_ok ? 1 : 0);
        if (poses_vec_ok) {
            fused_kernel<true, true><<<edgeBlocks + nodeBlocks, TPB>>>(
                edges, nodes, vels, poses, imu_drots, imu_dtrans, imu_dvels, dts,
                out_pg, out_adjvel, out_imurot, out_transvel, E, M, edgeBlocks);
        } else {
            fused_kernel<true, false><<<edgeBlocks + nodeBlocks, TPB>>>(
                edges, nodes, vels, poses, imu_drots, imu_dtrans, imu_dvels, dts,
                out_pg, out_adjvel, out_imurot, out_transvel, E, M, edgeBlocks);
        }
    } else {
        if (nodes_vec_ok && poses_vec_ok) {
            fused_kernel<false, true><<<edgeBlocks + nodeBlocks, TPB>>>(
                edges, nodes, vels, poses, imu_drots, imu_dtrans, imu_dvels, dts,
                out_pg, out_adjvel, out_imurot, out_transvel, E, M, edgeBlocks);
        } else {
            fused_kernel<false, false><<<edgeBlocks + nodeBlocks, TPB>>>(
                edges, nodes, vels, poses, imu_drots, imu_dtrans, imu_dvels, dts,
                out_pg, out_adjvel, out_imurot, out_transvel, E, M, edgeBlocks);
        }
    }
}